// round 14
// baseline (speedup 1.0000x reference)
#include <cuda_runtime.h>

// ---------------- problem constants ----------------
#define NLINES 2048
#define NEP    4096
#define NK     2048
#define NC     256
#define NTOT   6144
#define HC     128
#define WC     128
#define EB_CAP 512

// output offsets (float32, reference return-tuple order)
#define OFF_POINTS   0
#define OFF_SCORES   12288
#define OFF_DESCS    18432
#define OFF_NEWLINES 1591296
#define OFF_JIDX     1599488
#define OFF_LS       1603584

// fixed-point scales (commutative integer sums -> deterministic)
#define FX_COORD 65536.0f
#define FX_SCORE 33554432.0f

// ---------------- global scratch ----------------
__device__ int g_suppress[NK];
__device__ int g_edges[4 * EB_CAP];
__device__ int g_bcnt[4];
__device__ int g_ax[NEP];
__device__ int g_ay[NEP];
__device__ int g_as[NEP];
__device__ int g_cn[NEP];
__device__ int g_pre_done;      // 5 producers: 4 edge + 1 ls
__device__ int g_sup_done;      // 2 producers: suppression blocks
__device__ int g_geom_done;     // 1 producer: geom block
__device__ int g_sample_done;   // 256 producers: samplers

// =====================================================================
// k_reset: zero flags + segment accumulators (stream-ordered each replay)
// =====================================================================
__global__ void k_reset() {
    int i = blockIdx.x * 256 + threadIdx.x;   // 64 blocks -> 16384 threads
    g_ax[i] = 0; g_ay[i] = 0; g_as[i] = 0; g_cn[i] = 0;
    if (i == 0) { g_pre_done = 0; g_sup_done = 0; g_geom_done = 0; g_sample_done = 0; }
}

// =====================================================================
// k_all: 392 blocks x 512 thr, 64KB dyn smem — ALL wave-1 resident
//  (3 blocks/SM x 148 SMs = 444 slots >= 392: spins can never convoy)
//   [0,2)    : kp suppression (grid build; 1024 kp each) -> sup_done++
//   [2,6)    : edge build (grid build; 1024 eps each)    -> pre_done++
//   6        : line-score normalization                  -> pre_done++
//   7        : geom: spin pre_done==5 -> CC/rank/sums -> geom_done=1
//   [8,264)  : samplers: stage 64KB plane -> spin geom_done -> sample
//   [264,392): copy/normalize: spin sup_done -> copy -> spin sample_done
// =====================================================================
__global__ void __launch_bounds__(512) k_all(const float* __restrict__ lines,
                                             const float* __restrict__ line_sc,
                                             const float* __restrict__ kp,
                                             const float* __restrict__ ksc,
                                             const float* __restrict__ desc,
                                             const float* __restrict__ allD,
                                             float* __restrict__ out) {
    extern __shared__ int dsm[];
    int t = threadIdx.x;
    int role = blockIdx.x;
    const float2* ep2 = (const float2*)lines;

    if (role < 7 && role != 6) {
        // ============ grid-build roles (32x32 cells, cell=32) ============
        int*   ccn  = dsm;                     // 1024
        int*   cst  = dsm + 1024;              // 1024
        float* sx   = (float*)(dsm + 2048);    // 4096
        float* sy   = (float*)(dsm + 6144);    // 4096
        int*   sidx = dsm + 10240;             // 4096
        int*   scn  = dsm + 14336;             // 512
        int*   scnt = dsm + 14848;             // 1

        if (t == 0) scnt[0] = 0;
        for (int i = t; i < 1024; i += 512) ccn[i] = 0;
        __syncthreads();
        for (int i = t; i < 4096; i += 512) {
            float2 e = ep2[i];
            int cx = min(31, max(0, (int)(e.x * 0.03125f)));
            int cy = min(31, max(0, (int)(e.y * 0.03125f)));
            atomicAdd(&ccn[(cy << 5) | cx], 1);
        }
        __syncthreads();
        {   // exclusive scan (2/thread)
            int base = t * 2;
            int v0 = ccn[base], v1 = ccn[base + 1];
            int lsum = v0 + v1;
            scn[t] = lsum;
            __syncthreads();
            for (int off = 1; off < 512; off <<= 1) {
                int add = 0;
                if (t >= off) add = scn[t - off];
                __syncthreads();
                scn[t] += add;
                __syncthreads();
            }
            int excl = scn[t] - lsum;
            cst[base] = excl;
            cst[base + 1] = excl + v0;
        }
        __syncthreads();
        for (int i = t; i < 1024; i += 512) ccn[i] = 0;
        __syncthreads();
        for (int i = t; i < 4096; i += 512) {
            float2 e = ep2[i];
            int cx = min(31, max(0, (int)(e.x * 0.03125f)));
            int cy = min(31, max(0, (int)(e.y * 0.03125f)));
            int c = (cy << 5) | cx;
            int pos = cst[c] + atomicAdd(&ccn[c], 1);
            sx[pos] = e.x; sy[pos] = e.y; sidx[pos] = i;
        }
        __syncthreads();

        if (role < 2) {
            // ---- keypoint suppression: dist < 4 ----
            for (int it = 0; it < 2; ++it) {
                int k = role * 1024 + it * 512 + t;
                float kx = kp[2*k], ky = kp[2*k + 1];
                int x0 = max(0,  (int)floorf((kx - 4.f) * 0.03125f));
                int x1 = min(31, (int)floorf((kx + 4.f) * 0.03125f));
                int y0 = max(0,  (int)floorf((ky - 4.f) * 0.03125f));
                int y1 = min(31, (int)floorf((ky + 4.f) * 0.03125f));
                bool sup = false;
                for (int cy = y0; cy <= y1; ++cy)
                    for (int cx = x0; cx <= x1; ++cx) {
                        int c = (cy << 5) | cx;
                        int st = cst[c], en = st + ccn[c];
                        for (int j = st; j < en; ++j) {
                            float dx = kx - sx[j];
                            float dy = ky - sy[j];
                            if (dx*dx + dy*dy < 16.f) sup = true;
                        }
                    }
                g_suppress[k] = sup ? 1 : 0;
                out[OFF_POINTS + 2*(NEP + k)]     = sup ? 0.f : kx;
                out[OFF_POINTS + 2*(NEP + k) + 1] = sup ? 0.f : ky;
                out[OFF_SCORES + NEP + k]         = sup ? 0.f : ksc[k];
            }
            __threadfence();
            __syncthreads();
            if (t == 0) atomicAdd(&g_sup_done, 1);
        } else {
            // ---- edge build: d2 <= 9, i < j ----
            int b = role - 2;
            for (int it = 0; it < 2; ++it) {
                int i = b * 1024 + it * 512 + t;
                float2 e = ep2[i];
                int x0 = max(0,  (int)floorf((e.x - 3.f) * 0.03125f));
                int x1 = min(31, (int)floorf((e.x + 3.f) * 0.03125f));
                int y0 = max(0,  (int)floorf((e.y - 3.f) * 0.03125f));
                int y1 = min(31, (int)floorf((e.y + 3.f) * 0.03125f));
                for (int cy = y0; cy <= y1; ++cy)
                    for (int cx = x0; cx <= x1; ++cx) {
                        int c = (cy << 5) | cx;
                        int st = cst[c], en = st + ccn[c];
                        for (int j = st; j < en; ++j) {
                            int oj = sidx[j];
                            if (oj <= i) continue;
                            float dx = e.x - sx[j];
                            float dy = e.y - sy[j];
                            if (dx*dx + dy*dy <= 9.f) {
                                int x = atomicAdd(scnt, 1);
                                if (x < EB_CAP) g_edges[b * EB_CAP + x] = (i << 16) | oj;
                            }
                        }
                    }
            }
            __syncthreads();
            if (t == 0) g_bcnt[b] = scnt[0] < EB_CAP ? scnt[0] : EB_CAP;
            __threadfence();
            __syncthreads();
            if (t == 0) atomicAdd(&g_pre_done, 1);
        }
    } else if (role == 6) {
        // ============ line-score normalization ============
        float* red = (float*)dsm;
        float v = -1e30f;
        for (int k = t; k < NLINES; k += 512) v = fmaxf(v, line_sc[k]);
        red[t] = v;
        __syncthreads();
        for (int s = 256; s > 0; s >>= 1) {
            if (t < s) red[t] = fmaxf(red[t], red[t + s]);
            __syncthreads();
        }
        float denom = 1e-8f + red[0];
        for (int k = t; k < NLINES; k += 512) out[OFF_LS + k] = line_sc[k] / denom;
        __threadfence();
        __syncthreads();
        if (t == 0) atomicAdd(&g_pre_done, 1);
    } else if (role == 7) {
        // ============ geom (pure consumer of pre_done) ============
        int* lab  = dsm;             // 4096
        int* rnk  = dsm + 4096;      // 4096
        int* imap = dsm + 8192;      // 4096
        int* scn  = dsm + 12288;     // 512
        int* misc = dsm + 12800;     // 2

        for (int i = t; i < NEP; i += 512) { lab[i] = i; imap[i] = -1; }
        if (t == 0) {
            while (atomicAdd(&g_pre_done, 0) < 5) __nanosleep(128);
        }
        __syncthreads();
        __threadfence();

        // CC min-label fixpoint over 4 global edge segments (schedule-invariant)
        for (int it = 0; it < 64; ++it) {
            if (t == 0) misc[1] = 0;
            __syncthreads();
            #pragma unroll
            for (int b = 0; b < 4; ++b) {
                int cnt = g_bcnt[b];
                for (int e = t; e < cnt; e += 512) {
                    int pr = g_edges[b * EB_CAP + e];
                    int i = pr >> 16, j = pr & 0xffff;
                    int a = lab[i], bb = lab[j];
                    if (a < bb)      { int old = atomicMin(&lab[j], a); if (old > a) misc[1] = 1; }
                    else if (bb < a) { int old = atomicMin(&lab[i], bb); if (old > bb) misc[1] = 1; }
                }
            }
            __syncthreads();
            for (int i = t; i < NEP; i += 512) {
                int l = lab[i], l2 = lab[l];
                if (l2 < l) { lab[i] = l2; misc[1] = 1; }
            }
            __syncthreads();
            int ch = misc[1];
            __syncthreads();
            if (!ch) break;
        }

        // dense rank of roots (8 flags/thread, 512-scan)
        {
            int base = t * 8;
            int p8[8], pre[8], lsum = 0;
            #pragma unroll
            for (int k = 0; k < 8; ++k) {
                p8[k] = (lab[base + k] == base + k) ? 1 : 0;
                pre[k] = lsum;
                lsum += p8[k];
            }
            scn[t] = lsum;
            __syncthreads();
            for (int off = 1; off < 512; off <<= 1) {
                int add = 0;
                if (t >= off) add = scn[t - off];
                __syncthreads();
                scn[t] += add;
                __syncthreads();
            }
            int excl = scn[t] - lsum;
            #pragma unroll
            for (int k = 0; k < 8; ++k) rnk[base + k] = excl + pre[k];
        }
        __syncthreads();
        for (int i = t; i < NEP; i += 512)
            if (lab[i] == i) imap[rnk[i]] = i;
        __syncthreads();

        // fixed-point segment sums into global accumulators (zeroed by k_reset)
        for (int i = t; i < NEP; i += 512) {
            float2 e = ep2[i];
            float sc = out[OFF_LS + (i >> 1)];
            int r = lab[i];
            atomicAdd(&g_ax[r], __float2int_rn(e.x * FX_COORD));
            atomicAdd(&g_ay[r], __float2int_rn(e.y * FX_COORD));
            atomicAdd(&g_as[r], __float2int_rn(sc * FX_SCORE));
            atomicAdd(&g_cn[r], 1);
        }
        __syncthreads();   // block-local atomics now visible block-wide

        for (int s = t; s < NEP; s += 512) {
            int r = imap[s];
            float jx = 0.f, jy = 0.f, js = 0.f;
            if (r >= 0) {
                float ic = 1.0f / (float)g_cn[r];
                jx = (float)g_ax[r] * (1.0f / FX_COORD) * ic;
                jy = (float)g_ay[r] * (1.0f / FX_COORD) * ic;
                js = (float)g_as[r] * (1.0f / FX_SCORE) * ic;
            }
            out[OFF_POINTS + 2*s]     = jx;
            out[OFF_POINTS + 2*s + 1] = jy;
            out[OFF_SCORES + s]       = js;
        }
        for (int e = t; e < NEP; e += 512) {
            int r = lab[e];
            float ic = 1.0f / (float)g_cn[r];
            out[OFF_NEWLINES + 2*e]     = (float)g_ax[r] * (1.0f / FX_COORD) * ic;
            out[OFF_NEWLINES + 2*e + 1] = (float)g_ay[r] * (1.0f / FX_COORD) * ic;
            out[OFF_JIDX + e]           = (float)rnk[r];
        }
        __threadfence();
        __syncthreads();
        if (t == 0) atomicExch(&g_geom_done, 1);
    } else if (role < 264) {
        // ============ samplers: stage plane FIRST, then brief spin ============
        float* spl = (float*)dsm;               // 16384 floats = 64KB
        int ch = role - 8;
        const float4* src = (const float4*)(allD + (size_t)ch * (HC * WC));
        float4* dst = (float4*)spl;
        #pragma unroll
        for (int i = 0; i < 8; ++i) dst[i * 512 + t] = src[i * 512 + t];
        __syncthreads();

        if (t == 0) {
            while (atomicAdd(&g_geom_done, 0) == 0) __nanosleep(128);
        }
        __syncthreads();
        __threadfence();

        float* orow = out + OFF_DESCS + (size_t)ch * NTOT;
        const float2* pts = (const float2*)(out + OFF_POINTS);
        #pragma unroll
        for (int it = 0; it < 8; ++it) {
            int p = it * 512 + t;
            float2 pt = pts[p];
            float fx = ((pt.x - 3.5f) / 1019.5f) * 127.0f;   // folded (g+1)*0.5*(w-1)
            float fy = ((pt.y - 3.5f) / 1019.5f) * 127.0f;
            float x0 = fminf(fmaxf(floorf(fx), 0.f), 127.f);
            float y0 = fminf(fmaxf(floorf(fy), 0.f), 127.f);
            float x1 = fminf(x0 + 1.0f, 127.f);
            float y1 = fminf(y0 + 1.0f, 127.f);
            float wx = fx - x0;
            float wy = fy - y0;
            int a00 = (int)y0 * WC + (int)x0;
            int a01 = (int)y0 * WC + (int)x1;
            int a10 = (int)y1 * WC + (int)x0;
            int a11 = (int)y1 * WC + (int)x1;
            float v = spl[a00] * (1.f - wx) * (1.f - wy)
                    + spl[a01] * wx * (1.f - wy)
                    + spl[a10] * (1.f - wx) * wy
                    + spl[a11] * wx * wy;
            orow[p] = v;
        }
        __threadfence();
        __syncthreads();
        if (t == 0) atomicAdd(&g_sample_done, 1);
    } else {
        // ============ copy + normalize (consumers only) ============
        int cb = role - 264;                    // 0..127
        if (t == 0) {
            while (atomicAdd(&g_sup_done, 0) < 2) __nanosleep(128);
        }
        __syncthreads();
        __threadfence();

        const float4* d4 = (const float4*)desc;
        #pragma unroll
        for (int it = 0; it < 2; ++it) {
            int idx = cb * 1024 + it * 512 + t; // 131072 float4s total
            int c  = idx >> 9;
            int kq = idx & 511;
            float4 v = d4[c * 512 + kq];
            int k4 = kq * 4;
            if (g_suppress[k4])     v.x = 0.f;
            if (g_suppress[k4 + 1]) v.y = 0.f;
            if (g_suppress[k4 + 2]) v.z = 0.f;
            if (g_suppress[k4 + 3]) v.w = 0.f;
            float4* o4 = (float4*)(out + OFF_DESCS + c * NTOT + NEP);
            o4[kq] = v;
        }

        if (t == 0) {
            while (atomicAdd(&g_sample_done, 0) < 256) __nanosleep(256);
        }
        __syncthreads();
        __threadfence();

        int w = t >> 5, lane = t & 31;          // 16 warps x 16 channels
        int p = cb * 32 + lane;
        float* ob = out + OFF_DESCS + (size_t)w * 16 * NTOT + p;
        float v[16];
        float ssq = 0.f;
        #pragma unroll
        for (int ci = 0; ci < 16; ++ci) {
            float vv = ob[ci * NTOT];
            v[ci] = vv;
            ssq += vv * vv;
        }
        float* sred = (float*)dsm;              // [16][32]
        sred[w * 32 + lane] = ssq;
        __syncthreads();
        float tot = 0.f;
        #pragma unroll
        for (int i = 0; i < 16; ++i) tot += sred[i * 32 + lane];
        float inv = 1.0f / fmaxf(sqrtf(tot), 1e-12f);
        #pragma unroll
        for (int ci = 0; ci < 16; ++ci)
            ob[ci * NTOT] = v[ci] * inv;
    }
}

// ---------------- launch ----------------
extern "C" void kernel_launch(void* const* d_in, const int* in_sizes, int n_in,
                              void* d_out, int out_size) {
    const float* lines     = (const float*)d_in[0];
    const float* line_sc   = (const float*)d_in[1];
    const float* keypoints = (const float*)d_in[2];
    const float* kp_sc     = (const float*)d_in[3];
    const float* desc      = (const float*)d_in[4];
    const float* allD      = (const float*)d_in[5];
    float* out = (float*)d_out;

    static const int ALL_SMEM = HC * WC * 4;    // 64KB (sampler plane; max role)
    cudaFuncSetAttribute(k_all, cudaFuncAttributeMaxDynamicSharedMemorySize, ALL_SMEM);

    k_reset<<<64, 256>>>();
    k_all<<<392, 512, ALL_SMEM>>>(lines, line_sc, keypoints, kp_sc, desc, allD, out);
}

// round 15
// speedup vs baseline: 1.4007x; 1.4007x over previous
#include <cuda_runtime.h>

// ---------------- problem constants ----------------
#define NLINES 2048
#define NEP    4096
#define NK     2048
#define NC     256
#define NTOT   6144
#define HC     128
#define WC     128
#define EB_CAP 512
#define SE_CAP 1024

// output offsets (float32, reference return-tuple order)
#define OFF_POINTS   0
#define OFF_SCORES   12288
#define OFF_DESCS    18432
#define OFF_NEWLINES 1591296
#define OFF_JIDX     1599488
#define OFF_LS       1603584

// fixed-point scales (commutative integer sums -> deterministic)
#define FX_COORD 65536.0f
#define FX_SCORE 33554432.0f
#define FX_SSQ   268435456.0f     // 2^28; sum < 256*~20*2^28 << 2^64

// ---------------- global scratch ----------------
__device__ int g_suppress[NK];
__device__ int g_edges[4 * EB_CAP];
__device__ int g_bcnt[4];
__device__ unsigned long long g_ssq[NEP];
__device__ int g_pre_done;       // reset by k_main block 0 (stream-ordered)
__device__ int g_ssq_done;       // reset by k_geo ls role

// =====================================================================
// k_geo: 8 blocks x 1024 thr, ~123KB dyn smem.  (R13-proven)
//   [0,2) : kp suppression (grid build; 1024 kp each) + kp outputs
//   [2,6) : edge build (grid build; 1024 eps each) -> global lists
//   6     : line-score normalization + ssq/flag reset -> g_pre_done++
//   7     : geom: spins g_pre_done==5 (pure consumer) -> CC/rank/means
// =====================================================================
__global__ void __launch_bounds__(1024) k_geo(const float* __restrict__ lines,
                                              const float* __restrict__ line_sc,
                                              const float* __restrict__ kp,
                                              const float* __restrict__ ksc,
                                              float* __restrict__ out) {
    extern __shared__ int dsm[];
    int t = threadIdx.x;
    int role = blockIdx.x;
    const float2* ep2 = (const float2*)lines;

    if (role == 6) {
        // ---- ls-norm + resets for k_main ----
        if (t == 0) g_ssq_done = 0;
        for (int i = t; i < NEP; i += 1024) g_ssq[i] = 0ull;
        float* red = (float*)dsm;
        float v = -1e30f;
        for (int k = t; k < NLINES; k += 1024) v = fmaxf(v, line_sc[k]);
        red[t] = v;
        __syncthreads();
        for (int s = 512; s > 0; s >>= 1) {
            if (t < s) red[t] = fmaxf(red[t], red[t + s]);
            __syncthreads();
        }
        float denom = 1e-8f + red[0];
        for (int k = t; k < NLINES; k += 1024) out[OFF_LS + k] = line_sc[k] / denom;
        __threadfence();
        __syncthreads();
        if (t == 0) atomicAdd(&g_pre_done, 1);
        return;
    }

    if (role == 7) {
        // ================= geom (pure consumer) =================
        int* lab  = dsm;             // 4096
        int* rnk  = dsm + 4096;      // 4096
        int* imap = dsm + 8192;      // 4096
        int* ax   = dsm + 12288;     // 4096
        int* ay   = dsm + 16384;     // 4096
        int* as_  = dsm + 20480;     // 4096
        int* cn   = dsm + 24576;     // 4096
        int* sE   = dsm + 28672;     // SE_CAP
        int* scn  = dsm + 29696;     // 1024
        int* soff = dsm + 30720;     // 5
        int* misc = dsm + 30726;     // 2

        for (int i = t; i < NEP; i += 1024) {
            lab[i] = i;
            ax[i] = 0; ay[i] = 0; as_[i] = 0; cn[i] = 0; imap[i] = -1;
        }
        if (t == 0) {
            while (atomicAdd(&g_pre_done, 0) < 5) __nanosleep(128);
        }
        __syncthreads();
        __threadfence();

        if (t == 0) {
            int acc = 0;
            for (int b = 0; b < 4; ++b) { soff[b] = acc; acc += g_bcnt[b]; }
            soff[4] = acc;
        }
        __syncthreads();
        int E = soff[4]; if (E > SE_CAP) E = SE_CAP;
        for (int s = t; s < 4 * EB_CAP; s += 1024) {
            int b = s / EB_CAP, e = s % EB_CAP;
            if (e < g_bcnt[b]) { int d = soff[b] + e; if (d < SE_CAP) sE[d] = g_edges[s]; }
        }
        __syncthreads();

        // CC min-label fixpoint (schedule-invariant result)
        for (int it = 0; it < 64; ++it) {
            if (t == 0) misc[1] = 0;
            __syncthreads();
            for (int e = t; e < E; e += 1024) {
                int pr = sE[e];
                int i = pr >> 16, j = pr & 0xffff;
                int a = lab[i], b = lab[j];
                if (a < b)      { int old = atomicMin(&lab[j], a); if (old > a) misc[1] = 1; }
                else if (b < a) { int old = atomicMin(&lab[i], b); if (old > b) misc[1] = 1; }
            }
            __syncthreads();
            for (int i = t; i < NEP; i += 1024) {
                int l = lab[i], l2 = lab[l];
                if (l2 < l) { lab[i] = l2; misc[1] = 1; }
            }
            __syncthreads();
            int ch = misc[1];
            __syncthreads();
            if (!ch) break;
        }

        // dense rank of roots
        {
            int base = t * 4;
            int p4[4], pre[4], lsum = 0;
            #pragma unroll
            for (int k = 0; k < 4; ++k) {
                p4[k] = (lab[base + k] == base + k) ? 1 : 0;
                pre[k] = lsum;
                lsum += p4[k];
            }
            scn[t] = lsum;
            __syncthreads();
            for (int off = 1; off < 1024; off <<= 1) {
                int add = 0;
                if (t >= off) add = scn[t - off];
                __syncthreads();
                scn[t] += add;
                __syncthreads();
            }
            int excl = scn[t] - lsum;
            #pragma unroll
            for (int k = 0; k < 4; ++k) rnk[base + k] = excl + pre[k];
        }
        __syncthreads();
        for (int i = t; i < NEP; i += 1024)
            if (lab[i] == i) imap[rnk[i]] = i;
        __syncthreads();

        // fixed-point segment sums (smem atomics, commutative)
        for (int i = t; i < NEP; i += 1024) {
            float2 e = ep2[i];
            float sc = out[OFF_LS + (i >> 1)];
            int r = lab[i];
            atomicAdd(&ax[r],  __float2int_rn(e.x * FX_COORD));
            atomicAdd(&ay[r],  __float2int_rn(e.y * FX_COORD));
            atomicAdd(&as_[r], __float2int_rn(sc * FX_SCORE));
            atomicAdd(&cn[r], 1);
        }
        __syncthreads();

        for (int s = t; s < NEP; s += 1024) {
            int r = imap[s];
            float jx = 0.f, jy = 0.f, js = 0.f;
            if (r >= 0) {
                float ic = 1.0f / (float)cn[r];
                jx = (float)ax[r]  * (1.0f / FX_COORD) * ic;
                jy = (float)ay[r]  * (1.0f / FX_COORD) * ic;
                js = (float)as_[r] * (1.0f / FX_SCORE) * ic;
            }
            out[OFF_POINTS + 2*s]     = jx;
            out[OFF_POINTS + 2*s + 1] = jy;
            out[OFF_SCORES + s]       = js;
        }
        for (int e = t; e < NEP; e += 1024) {
            int r = lab[e];
            float ic = 1.0f / (float)cn[r];
            out[OFF_NEWLINES + 2*e]     = (float)ax[r] * (1.0f / FX_COORD) * ic;
            out[OFF_NEWLINES + 2*e + 1] = (float)ay[r] * (1.0f / FX_COORD) * ic;
            out[OFF_JIDX + e]           = (float)rnk[r];
        }
        return;
    }

    // ================= query blocks: redundant grid build =================
    int*   cst  = dsm;                    // 4096
    int*   ccn  = dsm + 4096;             // 4096
    float* sx   = (float*)(dsm + 8192);   // 4096
    float* sy   = (float*)(dsm + 12288);  // 4096
    int*   sidx = dsm + 16384;            // 4096
    int*   scn  = dsm + 20480;            // 1024
    int*   scnt = dsm + 21504;            // 1

    if (t == 0) scnt[0] = 0;
    for (int i = t; i < 4096; i += 1024) ccn[i] = 0;
    __syncthreads();
    for (int i = t; i < 4096; i += 1024) {
        float2 e = ep2[i];
        int cx = min(63, max(0, (int)(e.x * 0.0625f)));
        int cy = min(63, max(0, (int)(e.y * 0.0625f)));
        atomicAdd(&ccn[(cy << 6) | cx], 1);
    }
    __syncthreads();
    {
        int base = t * 4;
        int pre[4], lsum = 0;
        #pragma unroll
        for (int k = 0; k < 4; ++k) { pre[k] = lsum; lsum += ccn[base + k]; }
        scn[t] = lsum;
        __syncthreads();
        for (int off = 1; off < 1024; off <<= 1) {
            int add = 0;
            if (t >= off) add = scn[t - off];
            __syncthreads();
            scn[t] += add;
            __syncthreads();
        }
        int excl = scn[t] - lsum;
        #pragma unroll
        for (int k = 0; k < 4; ++k) cst[base + k] = excl + pre[k];
    }
    __syncthreads();
    for (int i = t; i < 4096; i += 1024) ccn[i] = 0;
    __syncthreads();
    for (int i = t; i < 4096; i += 1024) {
        float2 e = ep2[i];
        int cx = min(63, max(0, (int)(e.x * 0.0625f)));
        int cy = min(63, max(0, (int)(e.y * 0.0625f)));
        int c = (cy << 6) | cx;
        int pos = cst[c] + atomicAdd(&ccn[c], 1);
        sx[pos] = e.x; sy[pos] = e.y; sidx[pos] = i;
    }
    __syncthreads();

    if (role < 2) {
        // ---- keypoint suppression: dist < 4 ----
        int k = role * 1024 + t;
        float kx = kp[2*k], ky = kp[2*k + 1];
        int x0 = max(0,  (int)floorf((kx - 4.f) * 0.0625f));
        int x1 = min(63, (int)floorf((kx + 4.f) * 0.0625f));
        int y0 = max(0,  (int)floorf((ky - 4.f) * 0.0625f));
        int y1 = min(63, (int)floorf((ky + 4.f) * 0.0625f));
        bool sup = false;
        for (int cy = y0; cy <= y1; ++cy)
            for (int cx = x0; cx <= x1; ++cx) {
                int c = (cy << 6) | cx;
                int st = cst[c], en = st + ccn[c];
                for (int j = st; j < en; ++j) {
                    float dx = kx - sx[j];
                    float dy = ky - sy[j];
                    if (dx*dx + dy*dy < 16.f) sup = true;
                }
            }
        g_suppress[k] = sup ? 1 : 0;
        out[OFF_POINTS + 2*(NEP + k)]     = sup ? 0.f : kx;
        out[OFF_POINTS + 2*(NEP + k) + 1] = sup ? 0.f : ky;
        out[OFF_SCORES + NEP + k]         = sup ? 0.f : ksc[k];
    } else {
        // ---- edge build: d2 <= 9, i < j ----
        int b = role - 2;
        {
            int i = b * 1024 + t;
            float2 e = ep2[i];
            int x0 = max(0,  (int)floorf((e.x - 3.f) * 0.0625f));
            int x1 = min(63, (int)floorf((e.x + 3.f) * 0.0625f));
            int y0 = max(0,  (int)floorf((e.y - 3.f) * 0.0625f));
            int y1 = min(63, (int)floorf((e.y + 3.f) * 0.0625f));
            for (int cy = y0; cy <= y1; ++cy)
                for (int cx = x0; cx <= x1; ++cx) {
                    int c = (cy << 6) | cx;
                    int st = cst[c], en = st + ccn[c];
                    for (int j = st; j < en; ++j) {
                        int oj = sidx[j];
                        if (oj <= i) continue;
                        float dx = e.x - sx[j];
                        float dy = e.y - sy[j];
                        if (dx*dx + dy*dy <= 9.f) {
                            int x = atomicAdd(scnt, 1);
                            if (x < EB_CAP) g_edges[b * EB_CAP + x] = (i << 16) | oj;
                        }
                    }
                }
        }
        __syncthreads();
        if (t == 0) g_bcnt[b] = scnt[0] < EB_CAP ? scnt[0] : EB_CAP;
        __threadfence();
        __syncthreads();
        if (t == 0) atomicAdd(&g_pre_done, 1);
    }
}

// =====================================================================
// k_main: 384 blocks x 512 thr, 64KB dyn smem (all wave-1 resident)
//   [0,256)   : samplers: stage plane -> accumulate fixed-point ssq
//               (u64 atomics) -> ssq_done++ -> spin ssq_done==256 ->
//               recompute v from smem, write NORMALIZED. Single pass.
//   [256,384) : masked kp-desc float4 copy (no spins)
// =====================================================================
__global__ void __launch_bounds__(512) k_main(const float* __restrict__ allD,
                                              const float* __restrict__ desc,
                                              float* __restrict__ out) {
    extern __shared__ float spl[];      // 16384 floats = 64KB
    int t = threadIdx.x;
    int role = blockIdx.x;

    if (role == 0 && t == 0) g_pre_done = 0;   // reset for next replay's k_geo

    if (role < 256) {
        int ch = role;
        const float4* src = (const float4*)(allD + (size_t)ch * (HC * WC));
        float4* dst = (float4*)spl;
        #pragma unroll
        for (int i = 0; i < 8; ++i) dst[i * 512 + t] = src[i * 512 + t];
        __syncthreads();

        const float2* pts = (const float2*)(out + OFF_POINTS);
        // precompute per-point taps + v; contribute ssq
        float vs[8];
        #pragma unroll
        for (int it = 0; it < 8; ++it) {
            int p = it * 512 + t;
            float2 pt = pts[p];
            float fx = ((pt.x - 3.5f) / 1019.5f) * 127.0f;   // folded (g+1)*0.5*(w-1)
            float fy = ((pt.y - 3.5f) / 1019.5f) * 127.0f;
            float x0 = fminf(fmaxf(floorf(fx), 0.f), 127.f);
            float y0 = fminf(fmaxf(floorf(fy), 0.f), 127.f);
            float x1 = fminf(x0 + 1.0f, 127.f);
            float y1 = fminf(y0 + 1.0f, 127.f);
            float wx = fx - x0;
            float wy = fy - y0;
            int a00 = (int)y0 * WC + (int)x0;
            int a01 = (int)y0 * WC + (int)x1;
            int a10 = (int)y1 * WC + (int)x0;
            int a11 = (int)y1 * WC + (int)x1;
            float v = spl[a00] * (1.f - wx) * (1.f - wy)
                    + spl[a01] * wx * (1.f - wy)
                    + spl[a10] * (1.f - wx) * wy
                    + spl[a11] * wx * wy;
            vs[it] = v;
            atomicAdd(&g_ssq[p], (unsigned long long)__float2ull_rn(v * v * FX_SSQ));
        }
        __threadfence();
        __syncthreads();
        if (t == 0) {
            atomicAdd(&g_ssq_done, 1);
            while (atomicAdd(&g_ssq_done, 0) < 256) __nanosleep(256);
        }
        __syncthreads();
        __threadfence();

        float* orow = out + OFF_DESCS + (size_t)ch * NTOT;
        #pragma unroll
        for (int it = 0; it < 8; ++it) {
            int p = it * 512 + t;
            unsigned long long q = __ldcg(&g_ssq[p]);
            float ssq = (float)((double)q * (1.0 / (double)FX_SSQ));
            float inv = 1.0f / fmaxf(sqrtf(ssq), 1e-12f);
            orow[p] = vs[it] * inv;
        }
    } else {
        // ---- masked keypoint-descriptor copy (independent) ----
        int cb = role - 256;                    // 0..127
        const float4* d4 = (const float4*)desc;
        #pragma unroll
        for (int it = 0; it < 2; ++it) {
            int idx = cb * 1024 + it * 512 + t; // 131072 float4s total
            int c  = idx >> 9;
            int kq = idx & 511;
            float4 v = d4[c * 512 + kq];
            int k4 = kq * 4;
            if (g_suppress[k4])     v.x = 0.f;
            if (g_suppress[k4 + 1]) v.y = 0.f;
            if (g_suppress[k4 + 2]) v.z = 0.f;
            if (g_suppress[k4 + 3]) v.w = 0.f;
            float4* o4 = (float4*)(out + OFF_DESCS + c * NTOT + NEP);
            o4[kq] = v;
        }
    }
}

// ---------------- launch ----------------
extern "C" void kernel_launch(void* const* d_in, const int* in_sizes, int n_in,
                              void* d_out, int out_size) {
    const float* lines     = (const float*)d_in[0];
    const float* line_sc   = (const float*)d_in[1];
    const float* keypoints = (const float*)d_in[2];
    const float* kp_sc     = (const float*)d_in[3];
    const float* desc      = (const float*)d_in[4];
    const float* allD      = (const float*)d_in[5];
    float* out = (float*)d_out;

    static const int GEO_SMEM  = (30728 + 8) * 4;   // ~123 KB (max of roles)
    static const int MAIN_SMEM = HC * WC * 4;       // 64 KB
    cudaFuncSetAttribute(k_geo,  cudaFuncAttributeMaxDynamicSharedMemorySize, GEO_SMEM);
    cudaFuncSetAttribute(k_main, cudaFuncAttributeMaxDynamicSharedMemorySize, MAIN_SMEM);

    k_geo<<<8, 1024, GEO_SMEM>>>(lines, line_sc, keypoints, kp_sc, out);
    k_main<<<384, 512, MAIN_SMEM>>>(allD, desc, out);
}

// round 17
// speedup vs baseline: 1.4779x; 1.0551x over previous
#include <cuda_runtime.h>
#include <cstdint>

// ---------------- problem constants ----------------
#define NLINES 2048
#define NEP    4096
#define NK     2048
#define NC     256
#define NTOT   6144
#define HC     128
#define WC     128
#define EB_CAP 512
#define SE_CAP 1024

// output offsets (float32, reference return-tuple order)
#define OFF_POINTS   0
#define OFF_SCORES   12288
#define OFF_DESCS    18432
#define OFF_NEWLINES 1591296
#define OFF_JIDX     1599488
#define OFF_LS       1603584

// fixed-point scales (commutative integer sums -> deterministic)
#define FX_COORD 65536.0f
#define FX_SCORE 33554432.0f
#define FX_SSQ   268435456.0f     // 2^28

// ---------------- global scratch ----------------
__device__ int g_suppress[NK];
__device__ int g_edges[4 * EB_CAP];
__device__ int g_bcnt[4];
__device__ unsigned long long g_ssq[NEP];
__device__ int g_pre_done;       // reset by k_main block 0
__device__ int g_ssq_done;       // reset by k_geo ls role

__device__ __forceinline__ unsigned int smem_u32(const void* p) {
    unsigned int a;
    asm("{ .reg .u64 tt; cvta.to.shared.u64 tt, %1; cvt.u32.u64 %0, tt; }"
        : "=r"(a) : "l"(p));
    return a;
}

// =====================================================================
// k_geo: 8 blocks x 1024 thr, ~123KB dyn smem.  (R13/R15-proven)
//   [0,2) : kp suppression (grid build; 1024 kp each) + kp outputs
//   [2,6) : edge build (grid build; 1024 eps each) -> global lists
//   6     : line-score normalization + ssq/flag reset -> g_pre_done++
//   7     : geom: spins g_pre_done==5 (pure consumer) -> CC/rank/means
// =====================================================================
__global__ void __launch_bounds__(1024) k_geo(const float* __restrict__ lines,
                                              const float* __restrict__ line_sc,
                                              const float* __restrict__ kp,
                                              const float* __restrict__ ksc,
                                              float* __restrict__ out) {
    extern __shared__ int dsm[];
    int t = threadIdx.x;
    int role = blockIdx.x;
    const float2* ep2 = (const float2*)lines;

    if (role == 6) {
        // ---- ls-norm + resets for k_main ----
        if (t == 0) g_ssq_done = 0;
        for (int i = t; i < NEP; i += 1024) g_ssq[i] = 0ull;
        float* red = (float*)dsm;
        float v = -1e30f;
        for (int k = t; k < NLINES; k += 1024) v = fmaxf(v, line_sc[k]);
        red[t] = v;
        __syncthreads();
        for (int s = 512; s > 0; s >>= 1) {
            if (t < s) red[t] = fmaxf(red[t], red[t + s]);
            __syncthreads();
        }
        float denom = 1e-8f + red[0];
        for (int k = t; k < NLINES; k += 1024) out[OFF_LS + k] = line_sc[k] / denom;
        __threadfence();
        __syncthreads();
        if (t == 0) atomicAdd(&g_pre_done, 1);
        return;
    }

    if (role == 7) {
        // ================= geom (pure consumer) =================
        int* lab  = dsm;             // 4096
        int* rnk  = dsm + 4096;      // 4096
        int* imap = dsm + 8192;      // 4096
        int* ax   = dsm + 12288;     // 4096
        int* ay   = dsm + 16384;     // 4096
        int* as_  = dsm + 20480;     // 4096
        int* cn   = dsm + 24576;     // 4096
        int* sE   = dsm + 28672;     // SE_CAP
        int* scn  = dsm + 29696;     // 1024
        int* soff = dsm + 30720;     // 5
        int* misc = dsm + 30726;     // 2

        for (int i = t; i < NEP; i += 1024) {
            lab[i] = i;
            ax[i] = 0; ay[i] = 0; as_[i] = 0; cn[i] = 0; imap[i] = -1;
        }
        if (t == 0) {
            while (atomicAdd(&g_pre_done, 0) < 5) __nanosleep(128);
        }
        __syncthreads();
        __threadfence();

        if (t == 0) {
            int acc = 0;
            for (int b = 0; b < 4; ++b) { soff[b] = acc; acc += g_bcnt[b]; }
            soff[4] = acc;
        }
        __syncthreads();
        int E = soff[4]; if (E > SE_CAP) E = SE_CAP;
        for (int s = t; s < 4 * EB_CAP; s += 1024) {
            int b = s / EB_CAP, e = s % EB_CAP;
            if (e < g_bcnt[b]) { int d = soff[b] + e; if (d < SE_CAP) sE[d] = g_edges[s]; }
        }
        __syncthreads();

        for (int it = 0; it < 64; ++it) {
            if (t == 0) misc[1] = 0;
            __syncthreads();
            for (int e = t; e < E; e += 1024) {
                int pr = sE[e];
                int i = pr >> 16, j = pr & 0xffff;
                int a = lab[i], b = lab[j];
                if (a < b)      { int old = atomicMin(&lab[j], a); if (old > a) misc[1] = 1; }
                else if (b < a) { int old = atomicMin(&lab[i], b); if (old > b) misc[1] = 1; }
            }
            __syncthreads();
            for (int i = t; i < NEP; i += 1024) {
                int l = lab[i], l2 = lab[l];
                if (l2 < l) { lab[i] = l2; misc[1] = 1; }
            }
            __syncthreads();
            int ch = misc[1];
            __syncthreads();
            if (!ch) break;
        }

        {
            int base = t * 4;
            int p4[4], pre[4], lsum = 0;
            #pragma unroll
            for (int k = 0; k < 4; ++k) {
                p4[k] = (lab[base + k] == base + k) ? 1 : 0;
                pre[k] = lsum;
                lsum += p4[k];
            }
            scn[t] = lsum;
            __syncthreads();
            for (int off = 1; off < 1024; off <<= 1) {
                int add = 0;
                if (t >= off) add = scn[t - off];
                __syncthreads();
                scn[t] += add;
                __syncthreads();
            }
            int excl = scn[t] - lsum;
            #pragma unroll
            for (int k = 0; k < 4; ++k) rnk[base + k] = excl + pre[k];
        }
        __syncthreads();
        for (int i = t; i < NEP; i += 1024)
            if (lab[i] == i) imap[rnk[i]] = i;
        __syncthreads();

        for (int i = t; i < NEP; i += 1024) {
            float2 e = ep2[i];
            float sc = out[OFF_LS + (i >> 1)];
            int r = lab[i];
            atomicAdd(&ax[r],  __float2int_rn(e.x * FX_COORD));
            atomicAdd(&ay[r],  __float2int_rn(e.y * FX_COORD));
            atomicAdd(&as_[r], __float2int_rn(sc * FX_SCORE));
            atomicAdd(&cn[r], 1);
        }
        __syncthreads();

        for (int s = t; s < NEP; s += 1024) {
            int r = imap[s];
            float jx = 0.f, jy = 0.f, js = 0.f;
            if (r >= 0) {
                float ic = 1.0f / (float)cn[r];
                jx = (float)ax[r]  * (1.0f / FX_COORD) * ic;
                jy = (float)ay[r]  * (1.0f / FX_COORD) * ic;
                js = (float)as_[r] * (1.0f / FX_SCORE) * ic;
            }
            out[OFF_POINTS + 2*s]     = jx;
            out[OFF_POINTS + 2*s + 1] = jy;
            out[OFF_SCORES + s]       = js;
        }
        for (int e = t; e < NEP; e += 1024) {
            int r = lab[e];
            float ic = 1.0f / (float)cn[r];
            out[OFF_NEWLINES + 2*e]     = (float)ax[r] * (1.0f / FX_COORD) * ic;
            out[OFF_NEWLINES + 2*e + 1] = (float)ay[r] * (1.0f / FX_COORD) * ic;
            out[OFF_JIDX + e]           = (float)rnk[r];
        }
        return;
    }

    // ================= query blocks: redundant grid build =================
    int*   cst  = dsm;                    // 4096
    int*   ccn  = dsm + 4096;             // 4096
    float* sx   = (float*)(dsm + 8192);   // 4096
    float* sy   = (float*)(dsm + 12288);  // 4096
    int*   sidx = dsm + 16384;            // 4096
    int*   scn  = dsm + 20480;            // 1024
    int*   scnt = dsm + 21504;            // 1

    if (t == 0) scnt[0] = 0;
    for (int i = t; i < 4096; i += 1024) ccn[i] = 0;
    __syncthreads();
    for (int i = t; i < 4096; i += 1024) {
        float2 e = ep2[i];
        int cx = min(63, max(0, (int)(e.x * 0.0625f)));
        int cy = min(63, max(0, (int)(e.y * 0.0625f)));
        atomicAdd(&ccn[(cy << 6) | cx], 1);
    }
    __syncthreads();
    {
        int base = t * 4;
        int pre[4], lsum = 0;
        #pragma unroll
        for (int k = 0; k < 4; ++k) { pre[k] = lsum; lsum += ccn[base + k]; }
        scn[t] = lsum;
        __syncthreads();
        for (int off = 1; off < 1024; off <<= 1) {
            int add = 0;
            if (t >= off) add = scn[t - off];
            __syncthreads();
            scn[t] += add;
            __syncthreads();
        }
        int excl = scn[t] - lsum;
        #pragma unroll
        for (int k = 0; k < 4; ++k) cst[base + k] = excl + pre[k];
    }
    __syncthreads();
    for (int i = t; i < 4096; i += 1024) ccn[i] = 0;
    __syncthreads();
    for (int i = t; i < 4096; i += 1024) {
        float2 e = ep2[i];
        int cx = min(63, max(0, (int)(e.x * 0.0625f)));
        int cy = min(63, max(0, (int)(e.y * 0.0625f)));
        int c = (cy << 6) | cx;
        int pos = cst[c] + atomicAdd(&ccn[c], 1);
        sx[pos] = e.x; sy[pos] = e.y; sidx[pos] = i;
    }
    __syncthreads();

    if (role < 2) {
        int k = role * 1024 + t;
        float kx = kp[2*k], ky = kp[2*k + 1];
        int x0 = max(0,  (int)floorf((kx - 4.f) * 0.0625f));
        int x1 = min(63, (int)floorf((kx + 4.f) * 0.0625f));
        int y0 = max(0,  (int)floorf((ky - 4.f) * 0.0625f));
        int y1 = min(63, (int)floorf((ky + 4.f) * 0.0625f));
        bool sup = false;
        for (int cy = y0; cy <= y1; ++cy)
            for (int cx = x0; cx <= x1; ++cx) {
                int c = (cy << 6) | cx;
                int st = cst[c], en = st + ccn[c];
                for (int j = st; j < en; ++j) {
                    float dx = kx - sx[j];
                    float dy = ky - sy[j];
                    if (dx*dx + dy*dy < 16.f) sup = true;
                }
            }
        g_suppress[k] = sup ? 1 : 0;
        out[OFF_POINTS + 2*(NEP + k)]     = sup ? 0.f : kx;
        out[OFF_POINTS + 2*(NEP + k) + 1] = sup ? 0.f : ky;
        out[OFF_SCORES + NEP + k]         = sup ? 0.f : ksc[k];
    } else {
        int b = role - 2;
        {
            int i = b * 1024 + t;
            float2 e = ep2[i];
            int x0 = max(0,  (int)floorf((e.x - 3.f) * 0.0625f));
            int x1 = min(63, (int)floorf((e.x + 3.f) * 0.0625f));
            int y0 = max(0,  (int)floorf((e.y - 3.f) * 0.0625f));
            int y1 = min(63, (int)floorf((e.y + 3.f) * 0.0625f));
            for (int cy = y0; cy <= y1; ++cy)
                for (int cx = x0; cx <= x1; ++cx) {
                    int c = (cy << 6) | cx;
                    int st = cst[c], en = st + ccn[c];
                    for (int j = st; j < en; ++j) {
                        int oj = sidx[j];
                        if (oj <= i) continue;
                        float dx = e.x - sx[j];
                        float dy = e.y - sy[j];
                        if (dx*dx + dy*dy <= 9.f) {
                            int x = atomicAdd(scnt, 1);
                            if (x < EB_CAP) g_edges[b * EB_CAP + x] = (i << 16) | oj;
                        }
                    }
                }
        }
        __syncthreads();
        if (t == 0) g_bcnt[b] = scnt[0] < EB_CAP ? scnt[0] : EB_CAP;
        __threadfence();
        __syncthreads();
        if (t == 0) atomicAdd(&g_pre_done, 1);
    }
}

// =====================================================================
// k_main: 384 blocks x 512 thr, 64KB dyn smem
//   [0,256)   : samplers: TMA-stage plane (cp.async.bulk, no LSU cost),
//               prefetch points during transfer, sample, fixed-point ssq
//               atomics, tail ssq barrier, write normalized. Single pass.
//   [256,384) : masked kp-desc float4 copy (no spins)
// =====================================================================
__global__ void __launch_bounds__(512) k_main(const float* __restrict__ allD,
                                              const float* __restrict__ desc,
                                              float* __restrict__ out) {
    extern __shared__ float spl[];      // 16384 floats = 64KB
    __shared__ __align__(8) unsigned long long mbar;
    int t = threadIdx.x;
    int role = blockIdx.x;

    if (role == 0 && t == 0) g_pre_done = 0;   // reset for next replay's k_geo

    if (role < 256) {
        int ch = role;
        unsigned int mb = smem_u32(&mbar);
        unsigned int sm = smem_u32(spl);
        if (t == 0) {
            asm volatile("mbarrier.init.shared.b64 [%0], %1;" :: "r"(mb), "r"(1u) : "memory");
        }
        __syncthreads();
        if (t == 0) {
            asm volatile("mbarrier.arrive.expect_tx.shared.b64 _, [%0], %1;"
                         :: "r"(mb), "r"(65536u) : "memory");
            const char* src = (const char*)(allD + (size_t)ch * (HC * WC));
            #pragma unroll
            for (int c = 0; c < 4; ++c) {
                asm volatile(
                    "cp.async.bulk.shared::cta.global.mbarrier::complete_tx::bytes "
                    "[%0], [%1], %2, [%3];"
                    :: "r"(sm + c * 16384u), "l"(src + c * 16384), "r"(16384u), "r"(mb)
                    : "memory");
            }
        }

        // prefetch point coords while TMA flies
        const float2* pts = (const float2*)(out + OFF_POINTS);
        float2 mp[8];
        #pragma unroll
        for (int it = 0; it < 8; ++it) mp[it] = pts[it * 512 + t];

        // wait for plane
        {
            unsigned int done;
            do {
                asm volatile(
                    "{\n\t.reg .pred p;\n\t"
                    "mbarrier.try_wait.parity.acquire.cta.shared::cta.b64 p, [%1], %2, 0x989680;\n\t"
                    "selp.b32 %0, 1, 0, p;\n\t}"
                    : "=r"(done) : "r"(mb), "r"(0u) : "memory");
            } while (!done);
        }
        __syncthreads();

        float vs[8];
        #pragma unroll
        for (int it = 0; it < 8; ++it) {
            int p = it * 512 + t;
            float fx = ((mp[it].x - 3.5f) / 1019.5f) * 127.0f;   // folded (g+1)*0.5*(w-1)
            float fy = ((mp[it].y - 3.5f) / 1019.5f) * 127.0f;
            float x0 = fminf(fmaxf(floorf(fx), 0.f), 127.f);
            float y0 = fminf(fmaxf(floorf(fy), 0.f), 127.f);
            float x1 = fminf(x0 + 1.0f, 127.f);
            float y1 = fminf(y0 + 1.0f, 127.f);
            float wx = fx - x0;
            float wy = fy - y0;
            int a00 = (int)y0 * WC + (int)x0;
            int a01 = (int)y0 * WC + (int)x1;
            int a10 = (int)y1 * WC + (int)x0;
            int a11 = (int)y1 * WC + (int)x1;
            float v = spl[a00] * (1.f - wx) * (1.f - wy)
                    + spl[a01] * wx * (1.f - wy)
                    + spl[a10] * (1.f - wx) * wy
                    + spl[a11] * wx * wy;
            vs[it] = v;
            atomicAdd(&g_ssq[p], (unsigned long long)__float2ull_rn(v * v * FX_SSQ));
        }
        __threadfence();
        __syncthreads();
        if (t == 0) {
            atomicAdd(&g_ssq_done, 1);
            while (atomicAdd(&g_ssq_done, 0) < 256) __nanosleep(256);
        }
        __syncthreads();
        __threadfence();

        float* orow = out + OFF_DESCS + (size_t)ch * NTOT;
        #pragma unroll
        for (int it = 0; it < 8; ++it) {
            int p = it * 512 + t;
            unsigned long long q = __ldcg(&g_ssq[p]);
            float ssq = (float)((double)q * (1.0 / (double)FX_SSQ));
            float inv = 1.0f / fmaxf(sqrtf(ssq), 1e-12f);
            orow[p] = vs[it] * inv;
        }
    } else {
        // ---- masked keypoint-descriptor copy (independent) ----
        int cb = role - 256;                    // 0..127
        const float4* d4 = (const float4*)desc;
        #pragma unroll
        for (int it = 0; it < 2; ++it) {
            int idx = cb * 1024 + it * 512 + t; // 131072 float4s total
            int c  = idx >> 9;
            int kq = idx & 511;
            float4 v = d4[c * 512 + kq];
            int k4 = kq * 4;
            if (g_suppress[k4])     v.x = 0.f;
            if (g_suppress[k4 + 1]) v.y = 0.f;
            if (g_suppress[k4 + 2]) v.z = 0.f;
            if (g_suppress[k4 + 3]) v.w = 0.f;
            float4* o4 = (float4*)(out + OFF_DESCS + c * NTOT + NEP);
            o4[kq] = v;
        }
    }
}

// ---------------- launch ----------------
extern "C" void kernel_launch(void* const* d_in, const int* in_sizes, int n_in,
                              void* d_out, int out_size) {
    const float* lines     = (const float*)d_in[0];
    const float* line_sc   = (const float*)d_in[1];
    const float* keypoints = (const float*)d_in[2];
    const float* kp_sc     = (const float*)d_in[3];
    const float* desc      = (const float*)d_in[4];
    const float* allD      = (const float*)d_in[5];
    float* out = (float*)d_out;

    static const int GEO_SMEM  = (30728 + 8) * 4;   // ~123 KB (max of roles)
    static const int MAIN_SMEM = HC * WC * 4;       // 64 KB
    cudaFuncSetAttribute(k_geo,  cudaFuncAttributeMaxDynamicSharedMemorySize, GEO_SMEM);
    cudaFuncSetAttribute(k_main, cudaFuncAttributeMaxDynamicSharedMemorySize, MAIN_SMEM);

    k_geo<<<8, 1024, GEO_SMEM>>>(lines, line_sc, keypoints, kp_sc, out);
    k_main<<<384, 512, MAIN_SMEM>>>(allD, desc, out);
}